// round 2
// baseline (speedup 1.0000x reference)
#include <cuda_runtime.h>

typedef unsigned long long ull;

#define Lg 64
#define Bg 1024
#define CH 16
#define TH 16
#define NTILES (Lg/TH)          // 4
#define THREADS 288
#define R1 (TH+4)               // 20 conv1 output rows (halo 2)
#define R2 (TH+2)               // 18 conv2 output rows (halo 1)
#define RZ (TH+6)               // 22 input rows (halo 3)

// ---- dynamic shared memory layout ----
// float region
#define S1_OFF 0                         // 16*20*64 = 20480 floats
#define S2_OFF (CH*R1*Lg)                // +18432
#define SZ_OFF (S2_OFF + CH*R2*Lg)       // +1408
#define SB0_OFF (SZ_OFF + RZ*Lg)         // 16
#define SB1_OFF (SB0_OFF + 16)           // 16
#define SB2_OFF (SB1_OFF + 16)           // 1 (+pad)
#define FLT_END ((SB2_OFF + 2 + 1) & ~1) // even -> 8B aligned
#define U_BASE (FLT_END/2)
// ull region (weight pairs (w,w))
#define W1D 0                            // 2304
#define W0D 2304                         // 144
#define W2D (W0D+144)                    // 144
#define U_COUNT (W2D+144)
#define SMEM_BYTES ((size_t)(U_BASE + U_COUNT)*8)

// ---- packed f32x2 helpers (sm_100+) : per-lane exact fp32 FMA ----
__device__ __forceinline__ ull pk(float lo, float hi) {
    ull r; asm("mov.b64 %0, {%1, %2};" : "=l"(r) : "f"(lo), "f"(hi)); return r;
}
__device__ __forceinline__ void upk(ull v, float& lo, float& hi) {
    asm("mov.b64 {%0, %1}, %2;" : "=f"(lo), "=f"(hi) : "l"(v));
}
__device__ __forceinline__ void fma2(ull& d, ull a, ull b) {
    asm("fma.rn.f32x2 %0, %1, %2, %0;" : "+l"(d) : "l"(a), "l"(b));
}

// XLA EmitFastTanh replica (f32 rational approx, FMA Horner, clamp +-9,
// |x|<4e-4 passthrough). Division forced to IEEE rn.
__device__ __forceinline__ float xla_tanh(float x) {
    float ax = fabsf(x);
    float xc = fminf(fmaxf(x, -9.0f), 9.0f);
    float x2 = __fmul_rn(xc, xc);
    float p = -2.76076847742355e-16f;
    p = __fmaf_rn(p, x2,  2.00018790482477e-13f);
    p = __fmaf_rn(p, x2, -8.60467152213735e-11f);
    p = __fmaf_rn(p, x2,  5.12229709037114e-08f);
    p = __fmaf_rn(p, x2,  1.48572235717979e-05f);
    p = __fmaf_rn(p, x2,  6.37261928875436e-04f);
    p = __fmaf_rn(p, x2,  4.89352455891786e-03f);
    float num = __fmul_rn(xc, p);
    float q =  1.19825839466702e-06f;
    q = __fmaf_rn(q, x2,  1.18534705686654e-04f);
    q = __fmaf_rn(q, x2,  2.26843463243900e-03f);
    q = __fmaf_rn(q, x2,  4.89352518554385e-03f);
    float r = __fdiv_rn(num, q);
    return (ax < 0.0004f) ? x : r;
}

__global__ void copy_k(const float4* __restrict__ in, float4* __restrict__ out) {
    int i = blockIdx.x * blockDim.x + threadIdx.x;
    out[i] = in[i];
}

// One fused layer. All conv accumulations are single fp32 FMA chains starting
// at 0 in k = (dy, dx, ci) order (ci fastest), bias added afterwards —
// replicating XLA-CPU/Eigen im2col GEMM rounding exactly.
__global__ void __launch_bounds__(THREADS, 1)
layer_kernel(float* __restrict__ x,
             const float* __restrict__ w0, const float* __restrict__ b0,
             const float* __restrict__ w1, const float* __restrict__ b1,
             const float* __restrict__ w2, const float* __restrict__ b2,
             int parity)
{
    extern __shared__ float sm[];
    ull*   su = ((ull*)sm) + U_BASE;
    float* s1 = sm + S1_OFF;
    float* s2 = sm + S2_OFF;
    float* sz = sm + SZ_OFF;
    float* sb0 = sm + SB0_OFF;
    float* sb1 = sm + SB1_OFF;
    float* sb2 = sm + SB2_OFF;

    const int tid   = threadIdx.x;
    const int rbase = blockIdx.x * TH;
    const int xbase = ((int)blockIdx.y) << 12;   // b*4096

    // ---- Phase 0: weights (duplicated pairs) + biases + masked input tile ----
    for (int t = tid; t < 2304; t += THREADS) { float w = w1[t]; su[W1D + t] = pk(w, w); }
    for (int t = tid; t < 144;  t += THREADS) {
        float a = w0[t], b = w2[t];
        su[W0D + t] = pk(a, a);
        su[W2D + t] = pk(b, b);
    }
    if (tid < 16) { sb0[tid] = b0[tid]; sb1[tid] = b1[tid]; }
    if (tid == 0) { sb2[0] = b2[0]; }

    for (int t = tid; t < RZ * Lg; t += THREADS) {
        int rr = t >> 6, c = t & 63;
        int gr = (rbase + rr - 3) & 63;                 // periodic row wrap
        float v = x[xbase + (gr << 6) + c];
        sz[t] = (((gr + c) & 1) == parity) ? v : 0.0f;  // A-sites only
    }
    __syncthreads();

    // ---- Phase 1: conv1 (1 -> 16), chain over (dy,dx), + bias, tanh ----
    for (int task = tid; task < R1 * 16; task += THREADS) {
        int rr = task >> 4, c0 = (task & 15) << 2;
        int col[6];
        col[0] = (c0 + 63) & 63;
        col[1] = c0; col[2] = c0 + 1; col[3] = c0 + 2; col[4] = c0 + 3;
        col[5] = (c0 + 4) & 63;
        ull acc[32];
        #pragma unroll
        for (int i = 0; i < 32; i++) acc[i] = 0ull;
        #pragma unroll
        for (int dy = 0; dy < 3; dy++) {
            const float* rp = sz + ((rr + dy) << 6);
            float f[6];
            #pragma unroll
            for (int j = 0; j < 6; j++) f[j] = rp[col[j]];
            #pragma unroll
            for (int dx = 0; dx < 3; dx++) {
                ull qa = pk(f[dx],     f[dx + 1]);
                ull qb = pk(f[dx + 2], f[dx + 3]);
                const ull* wp = su + W0D + (dy * 3 + dx) * 16;
                #pragma unroll
                for (int co = 0; co < 16; co++) {
                    ull wd = wp[co];
                    fma2(acc[2*co],     wd, qa);
                    fma2(acc[2*co + 1], wd, qb);
                }
            }
        }
        #pragma unroll
        for (int co = 0; co < 16; co++) {
            float bb = sb0[co];
            float a0, a1, a2, a3;
            upk(acc[2*co], a0, a1); upk(acc[2*co + 1], a2, a3);
            float4 o = make_float4(xla_tanh(__fadd_rn(a0, bb)),
                                   xla_tanh(__fadd_rn(a1, bb)),
                                   xla_tanh(__fadd_rn(a2, bb)),
                                   xla_tanh(__fadd_rn(a3, bb)));
            *(float4*)(s1 + (co * R1 + rr) * Lg + c0) = o;
        }
    }
    __syncthreads();

    // ---- Phase 2: conv2 (16 -> 16), chain over (dy,dx,ci), + bias, tanh ----
    {
        int rr = tid >> 4, c0 = (tid & 15) << 2;
        int col[6];
        col[0] = (c0 + 63) & 63;
        col[1] = c0; col[2] = c0 + 1; col[3] = c0 + 2; col[4] = c0 + 3;
        col[5] = (c0 + 4) & 63;
        ull acc[32];
        #pragma unroll
        for (int i = 0; i < 32; i++) acc[i] = 0ull;
        #pragma unroll
        for (int dy = 0; dy < 3; dy++) {
            const float* rbp = s1 + (rr + dy) * Lg;
            #pragma unroll
            for (int dx = 0; dx < 3; dx++) {
                const ull* wbase = su + W1D + (dy * 3 + dx) * 256;
                #pragma unroll 4
                for (int ci = 0; ci < 16; ci++) {
                    const float* rp = rbp + ci * (R1 * Lg);
                    ull qa = pk(rp[col[dx]],     rp[col[dx + 1]]);
                    ull qb = pk(rp[col[dx + 2]], rp[col[dx + 3]]);
                    const ull* wp = wbase + ci * 16;
                    #pragma unroll
                    for (int co = 0; co < 16; co++) {
                        ull wd = wp[co];
                        fma2(acc[2*co],     wd, qa);
                        fma2(acc[2*co + 1], wd, qb);
                    }
                }
            }
        }
        #pragma unroll
        for (int co = 0; co < 16; co++) {
            float bb = sb1[co];
            float a0, a1, a2, a3;
            upk(acc[2*co], a0, a1); upk(acc[2*co + 1], a2, a3);
            float4 o = make_float4(xla_tanh(__fadd_rn(a0, bb)),
                                   xla_tanh(__fadd_rn(a1, bb)),
                                   xla_tanh(__fadd_rn(a2, bb)),
                                   xla_tanh(__fadd_rn(a3, bb)));
            *(float4*)(s2 + (co * R2 + rr) * Lg + c0) = o;
        }
    }
    __syncthreads();

    // ---- Phase 3: conv3 (16 -> 1), chain (dy,dx,ci), + bias, STE sign update ----
    if (tid < TH * 16) {
        int rr = tid >> 4, c0 = (tid & 15) << 2;
        int col[6];
        col[0] = (c0 + 63) & 63;
        col[1] = c0; col[2] = c0 + 1; col[3] = c0 + 2; col[4] = c0 + 3;
        col[5] = (c0 + 4) & 63;
        ull a0p = 0ull, a1p = 0ull;
        #pragma unroll
        for (int dy = 0; dy < 3; dy++) {
            const float* rbp = s2 + (rr + dy) * Lg;
            #pragma unroll
            for (int dx = 0; dx < 3; dx++) {
                const ull* wp = su + W2D + (dy * 3 + dx) * 16;
                #pragma unroll 4
                for (int ci = 0; ci < 16; ci++) {
                    const float* rp = rbp + ci * (R2 * Lg);
                    ull qa = pk(rp[col[dx]],     rp[col[dx + 1]]);
                    ull qb = pk(rp[col[dx + 2]], rp[col[dx + 3]]);
                    ull wd = wp[ci];
                    fma2(a0p, wd, qa);
                    fma2(a1p, wd, qb);
                }
            }
        }
        float l[4];
        {
            float bb = sb2[0];
            float u0, u1, u2, u3;
            upk(a0p, u0, u1); upk(a1p, u2, u3);
            l[0] = __fadd_rn(u0, bb);
            l[1] = __fadd_rn(u1, bb);
            l[2] = __fadd_rn(u2, bb);
            l[3] = __fadd_rn(u3, bb);
        }
        int gr = rbase + rr;
        int base = xbase + (gr << 6) + c0;
        #pragma unroll
        for (int px = 0; px < 4; px++) {
            if (((gr + c0 + px) & 1) != parity) {      // B-site
                float lv = l[px];
                float s = (lv > 0.0f) ? 1.0f : ((lv < 0.0f) ? -1.0f : 0.0f);
                // STE forward exactly as XLA computes it: l + (sign(l) - l)
                float m = __fadd_rn(lv, __fadd_rn(s, -lv));
                x[base + px] = __fmul_rn(x[base + px], m);
            }
        }
    }
}

extern "C" void kernel_launch(void* const* d_in, const int* in_sizes, int n_in,
                              void* d_out, int out_size)
{
    const float* z  = (const float*)d_in[0];
    const float* W0 = (const float*)d_in[1];
    const float* b0 = (const float*)d_in[2];
    const float* W1 = (const float*)d_in[3];
    const float* b1 = (const float*)d_in[4];
    const float* W2 = (const float*)d_in[5];
    const float* b2 = (const float*)d_in[6];
    float* x = (float*)d_out;

    cudaFuncSetAttribute(layer_kernel, cudaFuncAttributeMaxDynamicSharedMemorySize,
                         (int)SMEM_BYTES);

    // reset working state each replay: x <- z
    copy_k<<<(Bg * Lg * Lg) / (4 * 256), 256>>>((const float4*)z, (float4*)x);

    for (int i = 0; i < 4; i++) {
        layer_kernel<<<dim3(NTILES, Bg), THREADS, SMEM_BYTES>>>(
            x,
            W0 + i * 144, b0 + i * 16,
            W1 + i * 2304, b1 + i * 16,
            W2 + i * 144, b2 + i,
            i & 1);
    }
}

// round 3
// speedup vs baseline: 1.1883x; 1.1883x over previous
#include <cuda_runtime.h>

typedef unsigned long long ull;

#define Lg 64
#define Bg 1024
#define CH 16
#define TH 16
#define NTILES (Lg/TH)          // 4
#define THREADS 576
#define R1 (TH+4)               // 20 conv1 output rows (halo 2)
#define R2 (TH+2)               // 18 conv2 output rows (halo 1)
#define RZ (TH+6)               // 22 input rows (halo 3)

// ---- dynamic shared memory layout ----
// float region
#define S1_OFF 0                         // 16*20*64 = 20480 floats
#define S2_OFF (CH*R1*Lg)                // 20480 (+18432)
#define SZ_OFF (S2_OFF + CH*R2*Lg)       // 38912 (+1408)
#define SB0_OFF (SZ_OFF + RZ*Lg)         // 40320 (16)
#define SB1_OFF (SB0_OFF + 16)           // 40336 (16)
#define SB2_OFF (SB1_OFF + 16)           // 40352 (+2 pad)
#define FLT_END 40356                    // divisible by 4 -> ull region 16B aligned
#define U_BASE (FLT_END/2)               // 20178 (even)
// ull region (weight pairs (w,w))
#define W1D 0                            // 2304
#define W0D 2304                         // 144
#define W2D (W0D+144)                    // 144
#define U_COUNT (W2D+144)                // 2592
#define SMEM_BYTES ((size_t)(U_BASE + U_COUNT)*8)   // 182160 B

// ---- packed f32x2 helpers (sm_100+) : per-lane exact fp32 FMA ----
__device__ __forceinline__ ull pk(float lo, float hi) {
    ull r; asm("mov.b64 %0, {%1, %2};" : "=l"(r) : "f"(lo), "f"(hi)); return r;
}
__device__ __forceinline__ void upk(ull v, float& lo, float& hi) {
    asm("mov.b64 {%0, %1}, %2;" : "=f"(lo), "=f"(hi) : "l"(v));
}
__device__ __forceinline__ void fma2(ull& d, ull a, ull b) {
    asm("fma.rn.f32x2 %0, %1, %2, %0;" : "+l"(d) : "l"(a), "l"(b));
}

// XLA EmitFastTanh replica (f32 rational, FMA Horner, clamp +-9,
// |x|<4e-4 passthrough). Division forced to IEEE rn. DO NOT CHANGE.
__device__ __forceinline__ float xla_tanh(float x) {
    float ax = fabsf(x);
    float xc = fminf(fmaxf(x, -9.0f), 9.0f);
    float x2 = __fmul_rn(xc, xc);
    float p = -2.76076847742355e-16f;
    p = __fmaf_rn(p, x2,  2.00018790482477e-13f);
    p = __fmaf_rn(p, x2, -8.60467152213735e-11f);
    p = __fmaf_rn(p, x2,  5.12229709037114e-08f);
    p = __fmaf_rn(p, x2,  1.48572235717979e-05f);
    p = __fmaf_rn(p, x2,  6.37261928875436e-04f);
    p = __fmaf_rn(p, x2,  4.89352455891786e-03f);
    float num = __fmul_rn(xc, p);
    float q =  1.19825839466702e-06f;
    q = __fmaf_rn(q, x2,  1.18534705686654e-04f);
    q = __fmaf_rn(q, x2,  2.26843463243900e-03f);
    q = __fmaf_rn(q, x2,  4.89352518554385e-03f);
    float r = __fdiv_rn(num, q);
    return (ax < 0.0004f) ? x : r;
}

__global__ void copy_k(const float4* __restrict__ in, float4* __restrict__ out) {
    int i = blockIdx.x * blockDim.x + threadIdx.x;
    out[i] = in[i];
}

// One fused layer. All conv accumulations are single fp32 FMA chains starting
// at 0 in k = (dy, dx, ci) order (ci fastest), bias added afterwards —
// bit-identical to the XLA reference (verified rel_err == 0).
__global__ void __launch_bounds__(THREADS, 1)
layer_kernel(float* __restrict__ x,
             const float* __restrict__ w0, const float* __restrict__ b0,
             const float* __restrict__ w1, const float* __restrict__ b1,
             const float* __restrict__ w2, const float* __restrict__ b2,
             int parity)
{
    extern __shared__ float sm[];
    ull*   su = ((ull*)sm) + U_BASE;
    float* s1 = sm + S1_OFF;
    float* s2 = sm + S2_OFF;
    float* sz = sm + SZ_OFF;
    float* sb0 = sm + SB0_OFF;
    float* sb1 = sm + SB1_OFF;
    float* sb2 = sm + SB2_OFF;

    const int tid   = threadIdx.x;
    const int rbase = blockIdx.x * TH;
    const int xbase = ((int)blockIdx.y) << 12;   // b*4096

    // ---- Phase 0: weights (duplicated (w,w) pairs) + biases + masked tile ----
    for (int t = tid; t < 2304; t += THREADS) { float w = w1[t]; su[W1D + t] = pk(w, w); }
    for (int t = tid; t < 144;  t += THREADS) {
        float a = w0[t], b = w2[t];
        su[W0D + t] = pk(a, a);
        su[W2D + t] = pk(b, b);
    }
    if (tid < 16) { sb0[tid] = b0[tid]; sb1[tid] = b1[tid]; }
    if (tid == 0) { sb2[0] = b2[0]; }

    for (int t = tid; t < RZ * Lg; t += THREADS) {
        int rr = t >> 6, c = t & 63;
        int gr = (rbase + rr - 3) & 63;                 // periodic row wrap
        float v = x[xbase + (gr << 6) + c];
        sz[t] = (((gr + c) & 1) == parity) ? v : 0.0f;  // A-sites only
    }
    __syncthreads();

    // ---- Phase 1: conv1 (1 -> 16), chain (dy,dx), bias, tanh ----
    // 640 tasks: 20 rows x 16 col-groups(4px) x 2 co-halves
    for (int t = tid; t < R1 * 32; t += THREADS) {
        int rr = t >> 5, rem = t & 31;
        int c0 = (rem & 15) << 2;
        int coB = (rem >> 4) << 3;
        ull acc[16];
        #pragma unroll
        for (int i = 0; i < 16; i++) acc[i] = 0ull;
        #pragma unroll
        for (int dy = 0; dy < 3; dy++) {
            const float* rp = sz + ((rr + dy) << 6);
            float4 v = *(const float4*)(rp + c0);
            float lf = rp[(c0 + 63) & 63], rt = rp[(c0 + 4) & 63];
            ull qa[3] = { pk(lf, v.x),  pk(v.x, v.y), pk(v.y, v.z) };
            ull qb[3] = { pk(v.y, v.z), pk(v.z, v.w), pk(v.w, rt)  };
            #pragma unroll
            for (int dx = 0; dx < 3; dx++) {
                const ull* wp = su + W0D + (dy * 3 + dx) * 16 + coB;
                #pragma unroll
                for (int j = 0; j < 4; j++) {
                    ulonglong2 wv = *(const ulonglong2*)(wp + 2 * j);
                    fma2(acc[4*j + 0], wv.x, qa[dx]);
                    fma2(acc[4*j + 1], wv.x, qb[dx]);
                    fma2(acc[4*j + 2], wv.y, qa[dx]);
                    fma2(acc[4*j + 3], wv.y, qb[dx]);
                }
            }
        }
        #pragma unroll
        for (int j = 0; j < 8; j++) {
            float bb = sb0[coB + j];
            float a0, a1, a2, a3;
            upk(acc[2*j], a0, a1); upk(acc[2*j + 1], a2, a3);
            float4 o = make_float4(xla_tanh(__fadd_rn(a0, bb)),
                                   xla_tanh(__fadd_rn(a1, bb)),
                                   xla_tanh(__fadd_rn(a2, bb)),
                                   xla_tanh(__fadd_rn(a3, bb)));
            *(float4*)(s1 + ((coB + j) * R1 + rr) * Lg + c0) = o;
        }
    }
    __syncthreads();

    // ---- Phase 2: conv2 (16 -> 16), chain (dy,dx,ci), bias, tanh ----
    // exactly 576 tasks: 18 rows x 16 col-groups(4px) x 2 co-halves
    {
        int rr = tid >> 5, rem = tid & 31;
        int c0 = (rem & 15) << 2;
        int coB = (rem >> 4) << 3;
        int cm1 = (c0 + 63) & 63, cp4 = (c0 + 4) & 63;
        ull acc[16];
        #pragma unroll
        for (int i = 0; i < 16; i++) acc[i] = 0ull;
        #pragma unroll
        for (int dy = 0; dy < 3; dy++) {
            const float* rbp = s1 + (rr + dy) * Lg;
            #pragma unroll
            for (int dx = 0; dx < 3; dx++) {
                const ull* wbase = su + W1D + (dy * 3 + dx) * 256 + coB;
                #pragma unroll 4
                for (int ci = 0; ci < 16; ci++) {
                    const float* rp = rbp + ci * (R1 * Lg);
                    float4 v = *(const float4*)(rp + c0);
                    ull qa, qb;
                    if (dx == 0)      { qa = pk(rp[cm1], v.x); qb = pk(v.y, v.z); }
                    else if (dx == 1) { qa = pk(v.x, v.y);     qb = pk(v.z, v.w); }
                    else              { qa = pk(v.y, v.z);     qb = pk(v.w, rp[cp4]); }
                    const ull* wp = wbase + ci * 16;
                    #pragma unroll
                    for (int j = 0; j < 4; j++) {
                        ulonglong2 wv = *(const ulonglong2*)(wp + 2 * j);
                        fma2(acc[4*j + 0], wv.x, qa);
                        fma2(acc[4*j + 1], wv.x, qb);
                        fma2(acc[4*j + 2], wv.y, qa);
                        fma2(acc[4*j + 3], wv.y, qb);
                    }
                }
            }
        }
        #pragma unroll
        for (int j = 0; j < 8; j++) {
            float bb = sb1[coB + j];
            float a0, a1, a2, a3;
            upk(acc[2*j], a0, a1); upk(acc[2*j + 1], a2, a3);
            float4 o = make_float4(xla_tanh(__fadd_rn(a0, bb)),
                                   xla_tanh(__fadd_rn(a1, bb)),
                                   xla_tanh(__fadd_rn(a2, bb)),
                                   xla_tanh(__fadd_rn(a3, bb)));
            *(float4*)(s2 + ((coB + j) * R2 + rr) * Lg + c0) = o;
        }
    }
    __syncthreads();

    // ---- Phase 3: conv3 (16 -> 1), chain (dy,dx,ci), bias, STE sign update ----
    // 512 tasks: 16 rows x 32 col-groups(2px)
    if (tid < TH * 32) {
        int rr = tid >> 5;
        int c0 = (tid & 31) << 1;
        int cm1 = (c0 + 63) & 63, cp2 = (c0 + 2) & 63;
        ull acc = 0ull;
        #pragma unroll
        for (int dy = 0; dy < 3; dy++) {
            const float* rbp = s2 + (rr + dy) * Lg;
            #pragma unroll
            for (int dx = 0; dx < 3; dx++) {
                const ull* wp = su + W2D + (dy * 3 + dx) * 16;
                #pragma unroll 4
                for (int ci = 0; ci < 16; ci++) {
                    const float* rp = rbp + ci * (R2 * Lg);
                    float2 v = *(const float2*)(rp + c0);
                    ull qa;
                    if (dx == 0)      qa = pk(rp[cm1], v.x);
                    else if (dx == 1) qa = pk(v.x, v.y);
                    else              qa = pk(v.y, rp[cp2]);
                    fma2(acc, wp[ci], qa);
                }
            }
        }
        float bb = sb2[0];
        float u0, u1;
        upk(acc, u0, u1);
        float l[2];
        l[0] = __fadd_rn(u0, bb);
        l[1] = __fadd_rn(u1, bb);
        int gr = rbase + rr;
        int base = xbase + (gr << 6) + c0;
        #pragma unroll
        for (int px = 0; px < 2; px++) {
            if (((gr + c0 + px) & 1) != parity) {      // B-site
                float lv = l[px];
                float s = (lv > 0.0f) ? 1.0f : ((lv < 0.0f) ? -1.0f : 0.0f);
                // STE forward exactly as XLA computes it: l + (sign(l) - l)
                float m = __fadd_rn(lv, __fadd_rn(s, -lv));
                x[base + px] = __fmul_rn(x[base + px], m);
            }
        }
    }
}

extern "C" void kernel_launch(void* const* d_in, const int* in_sizes, int n_in,
                              void* d_out, int out_size)
{
    const float* z  = (const float*)d_in[0];
    const float* W0 = (const float*)d_in[1];
    const float* b0 = (const float*)d_in[2];
    const float* W1 = (const float*)d_in[3];
    const float* b1 = (const float*)d_in[4];
    const float* W2 = (const float*)d_in[5];
    const float* b2 = (const float*)d_in[6];
    float* x = (float*)d_out;

    cudaFuncSetAttribute(layer_kernel, cudaFuncAttributeMaxDynamicSharedMemorySize,
                         (int)SMEM_BYTES);

    // reset working state each replay: x <- z
    copy_k<<<(Bg * Lg * Lg) / (4 * 256), 256>>>((const float4*)z, (float4*)x);

    for (int i = 0; i < 4; i++) {
        layer_kernel<<<dim3(NTILES, Bg), THREADS, SMEM_BYTES>>>(
            x,
            W0 + i * 144, b0 + i * 16,
            W1 + i * 2304, b1 + i * 16,
            W2 + i * 144, b2 + i,
            i & 1);
    }
}

// round 4
// speedup vs baseline: 1.3371x; 1.1252x over previous
#include <cuda_runtime.h>

typedef unsigned long long ull;

#define Lg 64
#define Bg 1024
#define TH 16
#define NTILES (Lg/TH)          // 4
#define THREADS 576
#define R1 (TH+4)               // 20 conv1 output rows (halo 2)
#define R2 (TH+2)               // 18 conv2 output rows (halo 1)
#define RZ (TH+6)               // 22 input rows (halo 3)
#define PW 34                   // pairs per row: p = -1..32 (wrapped halo)

// ---- shared memory layout (ull units) ----
// activation planes stored as f32x2 pairs: pair p = (col p, col p+32)
#define S1U 0                               // 16*20*34 = 10880
#define S2U (S1U + 16*R1*PW)                // 10880 (+9792)
#define SZU (S2U + 16*R2*PW)                // 20672 (+748)
#define WU1 (SZU + RZ*PW)                   // 21420 (2304)
#define WU0 (WU1 + 2304)                    // 23724 (144)
#define WU2 (WU0 + 144)                     // 23868 (144)
#define BFU (WU2 + 144)                     // 24012 (biases: 33 floats -> 20 ull)
#define U_TOTAL (BFU + 20)                  // 24032
#define SMEM_BYTES ((size_t)U_TOTAL * 8)    // 192256 B

// ---- packed f32x2 helpers (sm_100+) : per-lane exact fp32 FMA ----
__device__ __forceinline__ ull pk(float lo, float hi) {
    ull r; asm("mov.b64 %0, {%1, %2};" : "=l"(r) : "f"(lo), "f"(hi)); return r;
}
__device__ __forceinline__ void upk(ull v, float& lo, float& hi) {
    asm("mov.b64 {%0, %1}, %2;" : "=f"(lo), "=f"(hi) : "l"(v));
}
__device__ __forceinline__ void fma2(ull& d, ull a, ull b) {
    asm("fma.rn.f32x2 %0, %1, %2, %0;" : "+l"(d) : "l"(a), "l"(b));
}

// XLA EmitFastTanh replica (f32 rational, FMA Horner, clamp +-9,
// |x|<4e-4 passthrough). Division forced to IEEE rn. DO NOT CHANGE.
__device__ __forceinline__ float xla_tanh(float x) {
    float ax = fabsf(x);
    float xc = fminf(fmaxf(x, -9.0f), 9.0f);
    float x2 = __fmul_rn(xc, xc);
    float p = -2.76076847742355e-16f;
    p = __fmaf_rn(p, x2,  2.00018790482477e-13f);
    p = __fmaf_rn(p, x2, -8.60467152213735e-11f);
    p = __fmaf_rn(p, x2,  5.12229709037114e-08f);
    p = __fmaf_rn(p, x2,  1.48572235717979e-05f);
    p = __fmaf_rn(p, x2,  6.37261928875436e-04f);
    p = __fmaf_rn(p, x2,  4.89352455891786e-03f);
    float num = __fmul_rn(xc, p);
    float q =  1.19825839466702e-06f;
    q = __fmaf_rn(q, x2,  1.18534705686654e-04f);
    q = __fmaf_rn(q, x2,  2.26843463243900e-03f);
    q = __fmaf_rn(q, x2,  4.89352518554385e-03f);
    float r = __fdiv_rn(num, q);
    return (ax < 0.0004f) ? x : r;
}

__global__ void copy_k(const float4* __restrict__ in, float4* __restrict__ out) {
    int i = blockIdx.x * blockDim.x + threadIdx.x;
    out[i] = in[i];
}

// One fused layer. All conv accumulations are single fp32 FMA chains starting
// at 0 in k = (dy, dx, ci) order (ci fastest), bias added afterwards —
// bit-identical to the XLA reference (verified rel_err == 0 in round 2/3).
__global__ void __launch_bounds__(THREADS, 1)
layer_kernel(float* __restrict__ x,
             const float* __restrict__ w0, const float* __restrict__ b0,
             const float* __restrict__ w1, const float* __restrict__ b1,
             const float* __restrict__ w2, const float* __restrict__ b2,
             int parity)
{
    extern __shared__ ull su[];
    float* sb = (float*)(su + BFU);      // sb[0..15]=b0, [16..31]=b1, [32]=b2

    const int tid   = threadIdx.x;
    const int rbase = blockIdx.x * TH;                 // even
    const int xbase = ((int)blockIdx.y) << 12;         // b*4096

    // ---- Phase 0: weights as duplicated (w,w) pairs + biases + packed input ----
    for (int t = tid; t < 2304; t += THREADS) { float w = w1[t]; su[WU1 + t] = pk(w, w); }
    for (int t = tid; t < 144;  t += THREADS) {
        float a = w0[t], b = w2[t];
        su[WU0 + t] = pk(a, a);
        su[WU2 + t] = pk(b, b);
    }
    if (tid < 16) { sb[tid] = b0[tid]; sb[16 + tid] = b1[tid]; }
    if (tid == 0) { sb[32] = b2[0]; }

    // packed masked input: entry e of row rr holds pair p = e-1:
    // ( z[gr][(p)&63], z[gr][(p+32)&63] ), zeroed at non-A sites.
    for (int t = tid; t < RZ * PW; t += THREADS) {
        int rr = t / PW, e = t - rr * PW, p = e - 1;
        int gr = (rbase + rr - 3) & 63;
        int c0 = p & 63, c1 = (p + 32) & 63;
        const float* row = x + xbase + (gr << 6);
        float v0 = row[c0], v1 = row[c1];
        v0 = (((gr + c0) & 1) == parity) ? v0 : 0.0f;
        v1 = (((gr + c1) & 1) == parity) ? v1 : 0.0f;
        su[SZU + t] = pk(v0, v1);
    }
    __syncthreads();

    // ---- Phase 1: conv1 (1 -> 16), chain (dy,dx), bias, tanh ----
    // 640 tasks: 20 rows x (16 pair-lanes x 2 co-halves)
    for (int t = tid; t < R1 * 32; t += THREADS) {
        int rr = t >> 5, rem = t & 31;
        int pA = rem & 15, pB = pA + 16;
        int coB = (rem >> 4) << 3;
        ull acc[16];
        #pragma unroll
        for (int i = 0; i < 16; i++) acc[i] = 0ull;
        #pragma unroll
        for (int dy = 0; dy < 3; dy++) {
            const ull* rp = su + SZU + (rr + dy) * PW + 1;
            #pragma unroll
            for (int dx = 0; dx < 3; dx++) {
                ull qa = rp[pA + dx - 1];
                ull qb = rp[pB + dx - 1];
                const ull* wp = su + WU0 + (dy * 3 + dx) * 16 + coB;
                #pragma unroll
                for (int j = 0; j < 4; j++) {
                    ulonglong2 wv = *(const ulonglong2*)(wp + 2 * j);
                    fma2(acc[4*j + 0], wv.x, qa);
                    fma2(acc[4*j + 1], wv.x, qb);
                    fma2(acc[4*j + 2], wv.y, qa);
                    fma2(acc[4*j + 3], wv.y, qb);
                }
            }
        }
        #pragma unroll
        for (int j = 0; j < 8; j++) {
            int co = coB + j;
            float bb = sb[co];
            // acc index: j = 2*jj + h -> acc[4*jj + 2*h + {0,1}]
            ull aA = acc[((j >> 1) << 2) + ((j & 1) << 1)];
            ull aB = acc[((j >> 1) << 2) + ((j & 1) << 1) + 1];
            float uA0, uA1, uB0, uB1;
            upk(aA, uA0, uA1); upk(aB, uB0, uB1);
            float tA0 = xla_tanh(__fadd_rn(uA0, bb));
            float tA1 = xla_tanh(__fadd_rn(uA1, bb));
            float tB0 = xla_tanh(__fadd_rn(uB0, bb));
            float tB1 = xla_tanh(__fadd_rn(uB1, bb));
            ull* op = su + S1U + (co * R1 + rr) * PW + 1;
            op[pA] = pk(tA0, tA1);
            op[pB] = pk(tB0, tB1);
            if (pA == 15) op[-1] = pk(tB1, tB0);   // wrapped halo (swap of pair 31)
            if (pA == 0)  op[32] = pk(tA1, tA0);   // wrapped halo (swap of pair 0)
        }
    }
    __syncthreads();

    // ---- Phase 2: conv2 (16 -> 16), chain (dy,dx,ci), bias, tanh ----
    // exactly 576 tasks: 18 rows x 16 pair-lanes x 2 co-halves
    {
        int rr = tid >> 5, rem = tid & 31;
        int pA = rem & 15, pB = pA + 16;
        int coB = (rem >> 4) << 3;
        ull acc[16];
        #pragma unroll
        for (int i = 0; i < 16; i++) acc[i] = 0ull;
        #pragma unroll
        for (int dy = 0; dy < 3; dy++) {
            const ull* rbp = su + S1U + (rr + dy) * PW + 1;
            #pragma unroll
            for (int dx = 0; dx < 3; dx++) {
                const ull* wb = su + WU1 + (dy * 3 + dx) * 256 + coB;
                #pragma unroll 4
                for (int ci = 0; ci < 16; ci++) {
                    const ull* rp = rbp + ci * (R1 * PW);
                    ull qa = rp[pA + dx - 1];
                    ull qb = rp[pB + dx - 1];
                    const ull* wp = wb + ci * 16;
                    #pragma unroll
                    for (int j = 0; j < 4; j++) {
                        ulonglong2 wv = *(const ulonglong2*)(wp + 2 * j);
                        fma2(acc[4*j + 0], wv.x, qa);
                        fma2(acc[4*j + 1], wv.x, qb);
                        fma2(acc[4*j + 2], wv.y, qa);
                        fma2(acc[4*j + 3], wv.y, qb);
                    }
                }
            }
        }
        #pragma unroll
        for (int j = 0; j < 8; j++) {
            int co = coB + j;
            float bb = sb[16 + co];
            ull aA = acc[((j >> 1) << 2) + ((j & 1) << 1)];
            ull aB = acc[((j >> 1) << 2) + ((j & 1) << 1) + 1];
            float uA0, uA1, uB0, uB1;
            upk(aA, uA0, uA1); upk(aB, uB0, uB1);
            float tA0 = xla_tanh(__fadd_rn(uA0, bb));
            float tA1 = xla_tanh(__fadd_rn(uA1, bb));
            float tB0 = xla_tanh(__fadd_rn(uB0, bb));
            float tB1 = xla_tanh(__fadd_rn(uB1, bb));
            ull* op = su + S2U + (co * R2 + rr) * PW + 1;
            op[pA] = pk(tA0, tA1);
            op[pB] = pk(tB0, tB1);
            if (pA == 15) op[-1] = pk(tB1, tB0);
            if (pA == 0)  op[32] = pk(tA1, tA0);
        }
    }
    __syncthreads();

    // ---- Phase 3: conv3 (16 -> 1), chain (dy,dx,ci), bias, STE sign update ----
    // 512 tasks: 16 rows x 32 pairs; pair p0 covers columns (p0, p0+32)
    if (tid < TH * 32) {
        int rr = tid >> 5;
        int p0 = tid & 31;
        ull acc = 0ull;
        #pragma unroll
        for (int dy = 0; dy < 3; dy++) {
            const ull* rbp = su + S2U + (rr + dy) * PW + 1;
            #pragma unroll
            for (int dx = 0; dx < 3; dx++) {
                const ull* wp = su + WU2 + (dy * 3 + dx) * 16;
                #pragma unroll 4
                for (int ci = 0; ci < 16; ci++) {
                    const ull* rp = rbp + ci * (R2 * PW);
                    fma2(acc, wp[ci], rp[p0 + dx - 1]);
                }
            }
        }
        float bb = sb[32];
        float u0, u1;
        upk(acc, u0, u1);
        float l0 = __fadd_rn(u0, bb);
        float l1 = __fadd_rn(u1, bb);
        int gr = rbase + rr;
        // columns p0 and p0+32 share parity -> uniform condition per thread
        if (((gr + p0) & 1) != parity) {
            float* row = x + xbase + (gr << 6);
            float s0 = (l0 > 0.0f) ? 1.0f : ((l0 < 0.0f) ? -1.0f : 0.0f);
            float s1v = (l1 > 0.0f) ? 1.0f : ((l1 < 0.0f) ? -1.0f : 0.0f);
            // STE forward exactly as XLA computes it: l + (sign(l) - l)
            float m0 = __fadd_rn(l0, __fadd_rn(s0, -l0));
            float m1 = __fadd_rn(l1, __fadd_rn(s1v, -l1));
            row[p0]      = __fmul_rn(row[p0],      m0);
            row[p0 + 32] = __fmul_rn(row[p0 + 32], m1);
        }
    }
}

extern "C" void kernel_launch(void* const* d_in, const int* in_sizes, int n_in,
                              void* d_out, int out_size)
{
    const float* z  = (const float*)d_in[0];
    const float* W0 = (const float*)d_in[1];
    const float* b0 = (const float*)d_in[2];
    const float* W1 = (const float*)d_in[3];
    const float* b1 = (const float*)d_in[4];
    const float* W2 = (const float*)d_in[5];
    const float* b2 = (const float*)d_in[6];
    float* x = (float*)d_out;

    cudaFuncSetAttribute(layer_kernel, cudaFuncAttributeMaxDynamicSharedMemorySize,
                         (int)SMEM_BYTES);

    // reset working state each replay: x <- z
    copy_k<<<(Bg * Lg * Lg) / (4 * 256), 256>>>((const float4*)z, (float4*)x);

    for (int i = 0; i < 4; i++) {
        layer_kernel<<<dim3(NTILES, Bg), THREADS, SMEM_BYTES>>>(
            x,
            W0 + i * 144, b0 + i * 16,
            W1 + i * 2304, b1 + i * 16,
            W2 + i * 144, b2 + i,
            i & 1);
    }
}